// round 10
// baseline (speedup 1.0000x reference)
#include <cuda_runtime.h>
#include <cstdint>

// out4[((b*H+y)*W+x)*768 + ch*4 + i] = float4{ in[b,ch,y+i-3, x-2..x+1] },
// zero-padded; lanes z,w zeroed when i==3. B=8, C=192, H=W=48.
// Block = (b, y, 4-wide x-tile). Output tile (TX*768 float4 = 48KB) is built in
// smem and stored with ONE async bulk copy (TMA) -> no per-thread STG stalls.

#define B_   8
#define C_   192
#define H_   48
#define W_   48
#define TX   4
#define XT   (W_ / TX)              // 12
#define PITCH 7                     // cols x0-2 .. x0+4 ; gcd(7,32)=1
#define SIN   (C_ * 4 * PITCH)      // 5376 floats  = 21504 B
#define SOUT4 (TX * C_ * 4)         // 3072 float4  = 49152 B
#define SMEM_BYTES (SIN * 4 + SOUT4 * 16)   // 70656 B
#define LOAD_ITERS (SIN / 256)      // 21

__global__ void __launch_bounds__(256)
block_sample_tma(const float* __restrict__ in, float4* __restrict__ out)
{
    extern __shared__ float smem[];
    float*  s    = smem;                                  // input tile
    float4* obuf = reinterpret_cast<float4*>(smem + SIN); // output tile

    const int tid = threadIdx.x;
    int bid = blockIdx.x;
    const int xt = bid % XT;  bid /= XT;
    const int y  = bid % H_;
    const int b  = bid / H_;
    const int x0 = xt * TX;

    // ---- load: rows y-3..y, cols x0-2..x0+4, all 192 channels ----
    #pragma unroll
    for (int k = 0; k < LOAD_ITERS; k++) {
        const int idx = k * 256 + tid;
        const int sc  = idx % PITCH;       // 0..6
        const int rf  = idx / PITCH;       // ch*4 + r
        const int gy  = y + (rf & 3) - 3;  // <= 47 always
        const int gx  = x0 - 2 + sc;       // -2 .. 48
        float v = 0.f;
        if (gy >= 0 && gx >= 0 && gx < W_)
            v = __ldg(in + ((b * C_ + (rf >> 2)) * H_ + gy) * W_ + gx);
        s[idx] = v;
    }
    __syncthreads();

    // ---- compute: per chi read 7-word window, emit TX sliding float4 to obuf ----
    #pragma unroll
    for (int sub = 0; sub < 3; sub++) {                 // 768 = 3*256
        const int chi = sub * 256 + tid;                // ch*4 + i
        const bool msk = (chi & 3) == 3;                // i == 3 -> mask z,w
        const float* row = &s[chi * PITCH];
        const float r0 = row[0], r1 = row[1], r2 = row[2], r3 = row[3];
        const float r4 = row[4], r5 = row[5], r6 = row[6];
        const float m2 = msk ? 0.f : r2;
        const float m3 = msk ? 0.f : r3;
        const float m4 = msk ? 0.f : r4;
        const float m5 = msk ? 0.f : r5;
        const float m6 = msk ? 0.f : r6;
        obuf[chi]               = make_float4(r0, r1, m2, m3);
        obuf[C_ * 4 + chi]      = make_float4(r1, r2, m3, m4);
        obuf[2 * C_ * 4 + chi]  = make_float4(r2, r3, m4, m5);
        obuf[3 * C_ * 4 + chi]  = make_float4(r3, r4, m5, m6);
    }

    // order generic-proxy smem writes before async-proxy bulk read
    asm volatile("fence.proxy.async.shared::cta;" ::: "memory");
    __syncthreads();

    // ---- one 48KB bulk store: smem -> contiguous global slab ----
    if (tid == 0) {
        float4* gdst = out + (long)((b * H_ + y) * W_ + x0) * (C_ * 4);
        uint32_t src = (uint32_t)__cvta_generic_to_shared(obuf);
        asm volatile(
            "cp.async.bulk.global.shared::cta.bulk_group [%0], [%1], %2;\n"
            :: "l"(gdst), "r"(src), "r"((int)(SOUT4 * 16)) : "memory");
        asm volatile("cp.async.bulk.commit_group;" ::: "memory");
        asm volatile("cp.async.bulk.wait_group 0;" ::: "memory");
    }
    __syncthreads();   // smem must outlive the bulk read
}

extern "C" void kernel_launch(void* const* d_in, const int* in_sizes, int n_in,
                              void* d_out, int out_size)
{
    const float* in  = (const float*)d_in[0];
    float4*      out = (float4*)d_out;

    cudaFuncSetAttribute(block_sample_tma,
                         cudaFuncAttributeMaxDynamicSharedMemorySize, SMEM_BYTES);

    const int blocks = B_ * H_ * XT;   // 4608
    block_sample_tma<<<blocks, 256, SMEM_BYTES>>>(in, out);
}

// round 11
// speedup vs baseline: 1.8133x; 1.8133x over previous
#include <cuda_runtime.h>

// out4[((b*H+y)*W+x)*768 + ch*4 + i] = float4{ in[b,ch,y+i-3, x-2..x+1] },
// zero-padded; lanes z,w zeroed when i==3. B=8, C=192, H=W=48.
// Block = (b, y, 12-wide x-tile, 96-channel half). Smem: [384 chi][15] = 23040 B.

#define B_     8
#define C_     192
#define H_     48
#define W_     48
#define TX     12
#define XT     (W_ / TX)            // 4 x-tiles
#define CSPL   2                    // channel splits per position
#define CH     (C_ / CSPL)          // 96 channels per block
#define ROWS   (CH * 4)             // 384 chi rows per block
#define PITCH  15                   // cols x0-2 .. x0+12 ; gcd(15,32)=1
#define SELEMS (ROWS * PITCH)       // 5760 floats = 23040 B
#define NTHR   192
#define LOAD_ITERS (SELEMS / NTHR)  // 30

__global__ void __launch_bounds__(NTHR)
block_sample_smem(const float* __restrict__ in, float4* __restrict__ out)
{
    __shared__ float s[SELEMS];

    const int tid = threadIdx.x;
    int bid = blockIdx.x;
    const int cs = bid & 1;   bid >>= 1;        // channel half
    const int xt = bid % XT;  bid /= XT;
    const int y  = bid % H_;
    const int b  = bid / H_;
    const int x0 = xt * TX;
    const int ch0 = cs * CH;

    // ---- load: rows y-3..y, cols x0-2..x0+12, channels ch0..ch0+95 ----
    #pragma unroll 10
    for (int k = 0; k < LOAD_ITERS; k++) {
        const int idx = k * NTHR + tid;
        const int sc  = idx % PITCH;       // 0..14
        const int rf  = idx / PITCH;       // ch_local*4 + r
        const int gy  = y + (rf & 3) - 3;  // <= 47 always
        const int gx  = x0 - 2 + sc;       // -2 .. 48
        float v = 0.f;
        if (gy >= 0 && gx >= 0 && gx < W_)
            v = __ldg(in + ((b * C_ + ch0 + (rf >> 2)) * H_ + gy) * W_ + gx);
        s[idx] = v;
    }
    __syncthreads();

    // ---- store: per chi read 15-word window (conflict-free scalar LDS),
    //      emit 12 independent, coalesced streaming STG.128 ----
    float4* const obase = out + (long)((b * H_ + y) * W_ + x0) * (C_ * 4) + ch0 * 4;
    #pragma unroll
    for (int sub = 0; sub < 2; sub++) {                 // 384 = 2*192
        const int chi = sub * NTHR + tid;               // ch_local*4 + i
        const bool msk = (chi & 3) == 3;                // i == 3 -> mask z,w
        const float* row = &s[chi * PITCH];

        float w[PITCH], wm[PITCH];
        #pragma unroll
        for (int c = 0; c < PITCH; c++) w[c] = row[c];
        #pragma unroll
        for (int c = 0; c < PITCH; c++) wm[c] = msk ? 0.f : w[c];

        float4* o = obase + chi;
        #pragma unroll
        for (int xl = 0; xl < TX; xl++) {
            __stcs(o + xl * (C_ * 4),
                   make_float4(w[xl], w[xl + 1], wm[xl + 2], wm[xl + 3]));
        }
    }
}

extern "C" void kernel_launch(void* const* d_in, const int* in_sizes, int n_in,
                              void* d_out, int out_size)
{
    const float* in  = (const float*)d_in[0];
    float4*      out = (float4*)d_out;

    const int blocks = B_ * H_ * XT * CSPL;   // 3072
    block_sample_smem<<<blocks, NTHR>>>(in, out);
}